// round 14
// baseline (speedup 1.0000x reference)
#include <cuda_runtime.h>
#include <math.h>
#include <stdint.h>

// Problem constants
#define TK   16384
#define HD   7168
#define NE   256
#define BT   128            // tokens per CTA
#define BE   64             // experts per CTA
#define BKS  64             // k per smem stage (two 32-k sub-chunks)
#define NST  (HD / BKS)     // 112 stages

// smem (floats): A [2][64][132] transposed, B [2][64][68] transposed
#define AP    132
#define BP    68
#define A_ST  (BKS * AP)                 // 8448 floats per stage
#define B_ST  (BKS * BP)                 // 4352
#define SMEM_FLOATS (2 * (A_ST + B_ST))  // 25600 floats = 102400 B

static __device__ float g_L[(size_t)TK * NE];   // fp32 logits scratch (16.8 MB)

// ---------------------------------------------------------------------------
// Packed fp32 (f32x2) helpers — Blackwell-native, both lanes IEEE RN.
// ---------------------------------------------------------------------------
#define FMA2(c, a, b) \
    asm("fma.rn.f32x2 %0, %1, %2, %0;" : "+l"(c) : "l"(a), "l"(b))
#define ADD2(c, s) \
    asm("add.rn.f32x2 %0, %1, %0;" : "+l"(c) : "l"(s))
#define PACK2(o, f) \
    asm("mov.b64 %0, {%1, %1};" : "=l"(o) : "r"(__float_as_uint(f)))

// Fast-math-immune ~1-ulp sigmoid (proved necessary in R3)
__device__ __forceinline__ float sigmoid_acc(float x)
{
    float t = -x;
    t = fminf(fmaxf(t, -80.0f), 80.0f);
    float n = rintf(t * 1.4426950408889634f);
    float r = fmaf(n, -0.693359375f, t);
    r = fmaf(n, 2.12194440e-4f, r);
    float p = 1.9841270e-4f;
    p = fmaf(p, r, 1.3888889e-3f);
    p = fmaf(p, r, 8.3333333e-3f);
    p = fmaf(p, r, 4.1666667e-2f);
    p = fmaf(p, r, 0.16666667f);
    p = fmaf(p, r, 0.5f);
    p = fmaf(p, r, 1.0f);
    p = fmaf(p, r, 1.0f);
    float e = p * __int_as_float(((int)n + 127) << 23);
    return __frcp_rn(1.0f + e);
}

// ---------------------------------------------------------------------------
// Kernel 1: fp32 GEMM via fma.rn.f32x2. Accumulation chain BIT-IDENTICAL to
// R3/R13: per logit, cacc over 32 ascending k (RN), mid += cacc per 32-chunk,
// acc += mid every 8 chunks. 64-k stages = two sub-chunks; chunk index
// cc = 2s+sub preserves the exact fold schedule.
// CTA: 128 tok x 64 exp, 256 threads, thread tile 4 tok x 8 exp (as pairs).
// Single __syncthreads per stage; double-buffered smem; reg-prefetched gmem.
// ---------------------------------------------------------------------------
__global__ __launch_bounds__(256, 1)
void gemm_kernel(const float* __restrict__ X, const float* __restrict__ W,
                 float* __restrict__ L)
{
    extern __shared__ float sm[];
    float* A_s = sm;                 // 2 stages of [64][132]  (k-major)
    float* B_s = sm + 2 * A_ST;      // 2 stages of [64][68]

    const int tid = threadIdx.x;
    const int tg  = tid & 31;        // token group: tokens 4tg..4tg+3
    const int wid = tid >> 5;        // expert group: experts 8wid..8wid+7
    const int t0  = blockIdx.x * BT;
    const int e0  = blockIdx.y * BE;

    // accumulators: [token][expert-pair] as f32x2
    uint64_t acc[4][4], mid[4][4];
    #pragma unroll
    for (int t = 0; t < 4; t++)
        #pragma unroll
        for (int p = 0; p < 4; p++) { acc[t][p] = 0ull; mid[t][p] = 0ull; }

    // A staging: token atok, k-half akseg (32 consecutive k = 8 float4)
    const int atok  = tid >> 1;
    const int akseg = tid & 1;
    const float* arow = X + (size_t)(t0 + atok) * HD + akseg * 32;

    // B staging: expert bexp, k-quarter bkseg (16 consecutive k = 4 float4)
    // STS banks: lanes have consecutive bexp -> conflict-free commits.
    const int bexp  = tid & 63;
    const int bkseg = tid >> 6;
    const float* brow = W + (size_t)(e0 + bexp) * HD + bkseg * 16;

    float4 areg[8], breg[4];

    auto loadStage = [&](int s) {
        const int off = s * BKS;
        #pragma unroll
        for (int j = 0; j < 8; j++)
            areg[j] = *(const float4*)(arow + off + j * 4);
        #pragma unroll
        for (int j = 0; j < 4; j++)
            breg[j] = *(const float4*)(brow + off + j * 4);
    };
    auto commitStage = [&](int buf) {
        float* Ab = A_s + buf * A_ST;
        float* Bb = B_s + buf * B_ST;
        #pragma unroll
        for (int j = 0; j < 8; j++) {
            const int kb = akseg * 32 + j * 4;
            Ab[(kb + 0) * AP + atok] = areg[j].x;
            Ab[(kb + 1) * AP + atok] = areg[j].y;
            Ab[(kb + 2) * AP + atok] = areg[j].z;
            Ab[(kb + 3) * AP + atok] = areg[j].w;
        }
        #pragma unroll
        for (int j = 0; j < 4; j++) {
            const int kb = bkseg * 16 + j * 4;
            Bb[(kb + 0) * BP + bexp] = breg[j].x;
            Bb[(kb + 1) * BP + bexp] = breg[j].y;
            Bb[(kb + 2) * BP + bexp] = breg[j].z;
            Bb[(kb + 3) * BP + bexp] = breg[j].w;
        }
    };

    // prologue: stage 0 into buf 0, prefetch stage 1 into regs
    loadStage(0);
    commitStage(0);
    if (NST > 1) loadStage(1);
    __syncthreads();

    for (int s = 0; s < NST; s++) {
        const int buf = s & 1;
        const float* Ab = A_s + buf * A_ST;
        const float* Bb = B_s + buf * B_ST;

        // compute two 32-k sub-chunks (chunk index cc = 2s+sub)
        #pragma unroll
        for (int sub = 0; sub < 2; sub++) {
            uint64_t cacc[4][4];
            #pragma unroll
            for (int t = 0; t < 4; t++)
                #pragma unroll
                for (int p = 0; p < 4; p++) cacc[t][p] = 0ull;

            #pragma unroll
            for (int k = 0; k < 32; k++) {
                const int kk = sub * 32 + k;
                const float4 a4 = *(const float4*)(Ab + kk * AP + 4 * tg);
                uint64_t a2[4];
                PACK2(a2[0], a4.x); PACK2(a2[1], a4.y);
                PACK2(a2[2], a4.z); PACK2(a2[3], a4.w);
                const ulonglong2 b01 = *(const ulonglong2*)(Bb + kk * BP + 8 * wid);
                const ulonglong2 b23 = *(const ulonglong2*)(Bb + kk * BP + 8 * wid + 4);
                const uint64_t b[4] = {b01.x, b01.y, b23.x, b23.y};
                #pragma unroll
                for (int t = 0; t < 4; t++)
                    #pragma unroll
                    for (int p = 0; p < 4; p++)
                        FMA2(cacc[t][p], a2[t], b[p]);
            }

            // mid += cacc; fold into acc every 8 chunks (R3 schedule)
            #pragma unroll
            for (int t = 0; t < 4; t++)
                #pragma unroll
                for (int p = 0; p < 4; p++) ADD2(mid[t][p], cacc[t][p]);
            const int cc = 2 * s + sub;
            if ((cc & 7) == 7) {
                #pragma unroll
                for (int t = 0; t < 4; t++)
                    #pragma unroll
                    for (int p = 0; p < 4; p++) {
                        ADD2(acc[t][p], mid[t][p]);
                        mid[t][p] = 0ull;
                    }
            }
        }

        // commit prefetched stage s+1 into the other buffer, prefetch s+2
        if (s + 1 < NST) {
            commitStage(buf ^ 1);
            if (s + 2 < NST) loadStage(s + 2);
        }
        __syncthreads();
    }

    // epilogue: unpack f32x2 lanes -> logits
    #pragma unroll
    for (int t = 0; t < 4; t++)
        #pragma unroll
        for (int p = 0; p < 4; p++) {
            uint32_t lo = (uint32_t)acc[t][p];
            uint32_t hi = (uint32_t)(acc[t][p] >> 32);
            float* dst = L + (size_t)(t0 + 4 * tg + t) * NE + e0 + 8 * wid + 2 * p;
            dst[0] = __uint_as_float(lo);
            dst[1] = __uint_as_float(hi);
        }
}

// ---------------------------------------------------------------------------
// Kernel 2: routing (ops identical to R3/R13). Warp routes a token.
// ---------------------------------------------------------------------------
__global__ __launch_bounds__(256, 4)
void route_kernel(const float* __restrict__ BIAS, float* __restrict__ out)
{
    const int wid = threadIdx.x >> 5;
    const int tx  = threadIdx.x & 31;
    const unsigned FULL = 0xffffffffu;

    for (int rr = 0; rr < 4; rr++) {
        const int tok = blockIdx.x * 32 + wid * 4 + rr;
        const float* Lrow = g_L + (size_t)tok * NE;

        float lgv[8], sfc[8];
        #pragma unroll
        for (int g = 0; g < 8; g++) {
            lgv[g] = Lrow[g * 32 + tx];
            sfc[g] = sigmoid_acc(lgv[g]) + __ldg(&BIAS[g * 32 + tx]);
        }

        float gs[8];
        #pragma unroll
        for (int g = 0; g < 8; g++) {
            float m1 = sfc[g], m2 = -3.4e38f;
            #pragma unroll
            for (int off = 16; off > 0; off >>= 1) {
                float o1 = __shfl_xor_sync(FULL, m1, off);
                float o2 = __shfl_xor_sync(FULL, m2, off);
                if (o1 > m1) { m2 = fmaxf(m1, o2); m1 = o1; }
                else         { m2 = fmaxf(m2, o1); }
            }
            gs[g] = m1 + m2;
        }

        unsigned gmask = 0;
        #pragma unroll
        for (int it = 0; it < 4; it++) {
            float best = -3.4e38f; int bg = 0;
            #pragma unroll
            for (int g = 0; g < 8; g++) {
                bool fr = !((gmask >> g) & 1);
                if (fr && gs[g] > best) { best = gs[g]; bg = g; }
            }
            gmask |= (1u << bg);
        }

        float val[8];
        #pragma unroll
        for (int g = 0; g < 8; g++)
            val[g] = ((gmask >> g) & 1) ? sfc[g] : 0.0f;

        float wts[8]; int ids[8]; float wsum = 0.0f;
        #pragma unroll
        for (int k = 0; k < 8; k++) {
            float bv = -3.4e38f; int be = 1 << 30;
            #pragma unroll
            for (int g = 0; g < 8; g++) {
                int e = g * 32 + tx;
                bool better = (val[g] > bv) || (val[g] == bv && e < be);
                if (better) { bv = val[g]; be = e; }
            }
            #pragma unroll
            for (int off = 16; off > 0; off >>= 1) {
                float ov = __shfl_xor_sync(FULL, bv, off);
                int   oe = __shfl_xor_sync(FULL, be, off);
                if (ov > bv || (ov == bv && oe < be)) { bv = ov; be = oe; }
            }
            const int cg = be >> 5, cl = be & 31;
            float sel = lgv[0];
            #pragma unroll
            for (int g = 1; g < 8; g++) if (g == cg) sel = lgv[g];
            float lg = __shfl_sync(FULL, sel, cl);
            float wgt = sigmoid_acc(lg);
            wts[k] = wgt; ids[k] = be; wsum += wgt;
            #pragma unroll
            for (int g = 0; g < 8; g++)
                if (g == cg && tx == cl) val[g] = -3.4e38f;
        }

        if (tx == 0) {
            float denom = wsum + 1e-20f;
            #pragma unroll
            for (int k = 0; k < 8; k++) {
                out[(size_t)tok * 8 + k] = (float)ids[k];
                out[(size_t)TK * 8 + (size_t)tok * 8 + k] = (wts[k] / denom) * 2.5f;
            }
        }
    }
}

extern "C" void kernel_launch(void* const* d_in, const int* in_sizes, int n_in,
                              void* d_out, int out_size)
{
    const float* X    = (const float*)d_in[0];   // [4,4096,7168] fp32
    const float* W    = (const float*)d_in[1];   // [256,7168]    fp32
    const float* BIAS = (const float*)d_in[2];   // [256]         fp32
    float* out = (float*)d_out;                  // idx block then weight block

    cudaFuncSetAttribute(gemm_kernel,
                         cudaFuncAttributeMaxDynamicSharedMemorySize,
                         SMEM_FLOATS * (int)sizeof(float));

    void* lptr = nullptr;
    cudaGetSymbolAddress(&lptr, g_L);
    float* L = (float*)lptr;

    dim3 grid(TK / BT, NE / BE);
    gemm_kernel<<<grid, 256, SMEM_FLOATS * sizeof(float)>>>(X, W, L);
    route_kernel<<<TK / 32, 256>>>(BIAS, out);
}